// round 5
// baseline (speedup 1.0000x reference)
#include <cuda_runtime.h>
#include <math_constants.h>

// Problem constants (NB, LQ, LK, DK, DV = 16, 384, 384, 64, 64)
#define NB 16
#define LQ 384
#define LK 384
#define DK 64
#define DV 64
#define QTA 6            // q-rows per block in the attn kernel (384/6=64 -> 1024 blocks, 6.92/SM)
#define INV_TEMP 0.125f  // 1 / TEMPERATURE, TEMPERATURE = 8.0

// Scratch for attn probabilities in case the harness output only holds `output`.
__device__ float g_attn_scratch[NB * LQ * LK];

// ---------------------------------------------------------------------------
// Kernel A: attn[n,q,k] = softmax_k( (q[n,q,:] . k[n,k,:]) / 8 )
// grid = (LQ/QTA=64, NB=16) = 1024 blocks, block = 128 threads.
// Each thread owns 3 K-rows (k = tid, tid+128, tid+256); per K-row it streams
// 16 float4 loads and accumulates 6 dot products against the q-tile staged in
// shared memory (broadcast LDS.128). Then one warp per q-row does softmax.
// 1024 blocks / 148 SMs = 6.92 -> ceil 7 => ~1% wave imbalance (the R3 attn
// kernel had 192 blocks -> 1-or-2 per SM -> ~54% imbalance; that was the bug).
// ---------------------------------------------------------------------------
__global__ __launch_bounds__(128, 8)
void attn_kernel(const float* __restrict__ q,
                 const float* __restrict__ k,
                 float* __restrict__ attn_ext)
{
    __shared__ float4 qs4[QTA][DK / 4];      // 6 x 64 floats = 1.5 KB
    __shared__ float  scores[QTA][LK];       // 9 KB

    float* attn = attn_ext ? attn_ext : g_attn_scratch;

    const int n   = blockIdx.y;
    const int q0  = blockIdx.x * QTA;
    const int tid = threadIdx.x;             // 0..127

    // Stage the 6 q-rows (96 float4) into shared memory.
    {
        const float4* qsrc = reinterpret_cast<const float4*>(
            q + ((size_t)n * LQ + q0) * DK);
        if (tid < QTA * (DK / 4))
            qs4[tid >> 4][tid & 15] = qsrc[tid];
    }
    __syncthreads();

    // Scores: 3 K-rows per thread, 6 q accumulators each.
#pragma unroll
    for (int kk = 0; kk < 3; kk++) {
        const int kidx = tid + kk * 128;
        const float4* krow = reinterpret_cast<const float4*>(
            k + ((size_t)n * LK + kidx) * DK);

        float acc[QTA];
#pragma unroll
        for (int qq = 0; qq < QTA; qq++) acc[qq] = 0.0f;

#pragma unroll
        for (int i = 0; i < DK / 4; i++) {
            const float4 kv = krow[i];
#pragma unroll
            for (int qq = 0; qq < QTA; qq++) {
                const float4 a = qs4[qq][i];   // warp-broadcast LDS.128
                acc[qq] += a.x * kv.x + a.y * kv.y + a.z * kv.z + a.w * kv.w;
            }
        }
#pragma unroll
        for (int qq = 0; qq < QTA; qq++)
            scores[qq][kidx] = acc[qq] * INV_TEMP;
    }
    __syncthreads();

    // Softmax: 4 warps cover the 6 rows (warp w handles rows w, w+4).
    const int warp = tid >> 5;
    const int lane = tid & 31;
    for (int qq = warp; qq < QTA; qq += 4) {
        const float* row = scores[qq];

        float m = -CUDART_INF_F;
#pragma unroll
        for (int j = 0; j < LK / 32; j++) m = fmaxf(m, row[lane + j * 32]);
#pragma unroll
        for (int s = 16; s > 0; s >>= 1)
            m = fmaxf(m, __shfl_xor_sync(0xFFFFFFFFu, m, s));

        float e[LK / 32];
        float sum = 0.0f;
#pragma unroll
        for (int j = 0; j < LK / 32; j++) {
            e[j] = __expf(row[lane + j * 32] - m);
            sum += e[j];
        }
#pragma unroll
        for (int s = 16; s > 0; s >>= 1)
            sum += __shfl_xor_sync(0xFFFFFFFFu, sum, s);
        const float inv = 1.0f / sum;

        float* arow = attn + ((size_t)n * LQ + q0 + qq) * LK;
#pragma unroll
        for (int j = 0; j < LK / 32; j++)
            arow[lane + j * 32] = e[j] * inv;
    }
}

// ---------------------------------------------------------------------------
// Kernel B (UNCHANGED from R3 — measured 92.3us @ 84.6% DRAM, 6.7 TB/s):
// out[n,q,d] = sum_k attn[n,q,k] * rel_pos_v[n,q,k,d]
// ---------------------------------------------------------------------------
__global__ __launch_bounds__(256, 8)
void out_kernel(const float* __restrict__ attn_ext_is_null_marker, // unused
                const float* __restrict__ rpv,
                float* __restrict__ out,
                const float* __restrict__ attn_ext)
{
    __shared__ float  sa[LK];       // attn row, 1.5 KB
    __shared__ float4 rbuf[256];    // reduction buffer, 4 KB

    const float* attn = attn_ext ? attn_ext : g_attn_scratch;

    const int nq  = blockIdx.x;            // n*LQ + q
    const int tid = threadIdx.x;

    {
        const float* arow = attn + (size_t)nq * LK;
        for (int j = tid; j < LK; j += 256) sa[j] = arow[j];
    }
    __syncthreads();

    const int d4 = tid & 15;   // float4 column (d = 4*d4 .. 4*d4+3)
    const int kk = tid >> 4;   // k-slice start (k = kk, kk+16, ...)

    const float4* base = reinterpret_cast<const float4*>(
        rpv + (size_t)nq * LK * DV);

    float4 acc = make_float4(0.f, 0.f, 0.f, 0.f);
#pragma unroll
    for (int i = 0; i < LK / 16; i++) {          // 24 iterations
        const int kidx = kk + i * 16;
        const float  a = sa[kidx];
        const float4 v = base[kidx * (DV / 4) + d4];
        acc.x += a * v.x;
        acc.y += a * v.y;
        acc.z += a * v.z;
        acc.w += a * v.w;
    }

    rbuf[tid] = acc;
    __syncthreads();

#pragma unroll
    for (int s = 128; s >= 16; s >>= 1) {
        if (tid < s) {
            float4 a = rbuf[tid];
            float4 b = rbuf[tid + s];
            a.x += b.x; a.y += b.y; a.z += b.z; a.w += b.w;
            rbuf[tid] = a;
        }
        __syncthreads();
    }

    if (tid < DV) {
        out[(size_t)nq * DV + tid] = reinterpret_cast<const float*>(rbuf)[tid];
    }
}

// ---------------------------------------------------------------------------
// Launch. Inputs (metadata order) = q, k, v, rel_pos, rel_pos_v.
// v and rel_pos are unused by the reference — never touched.
// Output layout: [output (NB*LQ*DV) | attn (NB*LQ*LK)] when out_size covers
// both (this branch was taken in R3 and passed); otherwise attn -> scratch.
// ---------------------------------------------------------------------------
extern "C" void kernel_launch(void* const* d_in, const int* in_sizes, int n_in,
                              void* d_out, int out_size)
{
    const float* q   = (const float*)d_in[0];
    const float* k   = (const float*)d_in[1];
    const float* rpv = (const float*)d_in[4];
    float* out = (float*)d_out;

    const long long out_elems  = (long long)NB * LQ * DV;   // 393216
    const long long attn_elems = (long long)NB * LQ * LK;   // 2359296

    float* attn_ext = nullptr;  // null -> kernels fall back to g_attn_scratch
    if ((long long)out_size >= out_elems + attn_elems) {
        attn_ext = out + out_elems;
    }

    dim3 gridA(LQ / QTA, NB);
    attn_kernel<<<gridA, 128>>>(q, k, attn_ext);

    out_kernel<<<NB * LQ, 256>>>(nullptr, rpv, out, attn_ext);
}

// round 6
// speedup vs baseline: 1.8395x; 1.8395x over previous
#include <cuda_runtime.h>
#include <math_constants.h>

// Problem constants (NB, LQ, LK, DK, DV = 16, 384, 384, 64, 64)
#define NB 16
#define LQ 384
#define LK 384
#define DK 64
#define DV 64
#define QTA 6            // q-rows per attn block (384/6=64 -> 1024 blocks, 6.92/SM)
#define KC  128          // K-chunk rows staged in smem per iteration
#define INV_TEMP 0.125f  // 1 / TEMPERATURE, TEMPERATURE = 8.0

// Scratch for attn probabilities in case the harness output only holds `output`.
__device__ float g_attn_scratch[NB * LQ * LK];

// ---------------------------------------------------------------------------
// Kernel A: attn[n,q,k] = softmax_k( (q[n,q,:] . k[n,k,:]) / 8 )
// grid = (64, 16) = 1024 blocks, 128 threads.
// R4's fatal flaw: per-thread K-row LDGs were fully uncoalesced (32 L1tex
// wavefronts per LDG.128). Fix: K is staged into shared memory in 3 chunks of
// 128 rows with fully COALESCED float4 loads, using an XOR bank swizzle
// (column d4 ^ (k&7)) so both the staging stores and the per-thread row reads
// are conflict-free (each 8-lane LDS.128 phase hits 8 distinct bank groups).
// Compute: thread t owns k-row t of the chunk, 6 q accumulators, q broadcast
// from smem. FFMA-pipe bound (~9us floor chip-wide).
// ---------------------------------------------------------------------------
__global__ __launch_bounds__(128, 5)
void attn_kernel(const float* __restrict__ q,
                 const float* __restrict__ k,
                 float* __restrict__ attn_ext)
{
    __shared__ float4 qs4[QTA][DK / 4];      // 1.5 KB
    __shared__ float4 ks4[KC][DK / 4];       // 32 KB, XOR-swizzled columns
    __shared__ float  scores[QTA][LK];       // 9 KB

    float* attn = attn_ext ? attn_ext : g_attn_scratch;

    const int n   = blockIdx.y;
    const int q0  = blockIdx.x * QTA;
    const int tid = threadIdx.x;             // 0..127

    // Stage the 6 q-rows (96 float4, coalesced).
    {
        const float4* qsrc = reinterpret_cast<const float4*>(
            q + ((size_t)n * LQ + q0) * DK);
        if (tid < QTA * (DK / 4))
            qs4[tid >> 4][tid & 15] = qsrc[tid];
    }

    const float4* ksrc = reinterpret_cast<const float4*>(
        k + (size_t)n * LK * DK);

#pragma unroll
    for (int c = 0; c < LK / KC; c++) {      // 3 chunks
        __syncthreads();   // protects qs4 (1st iter) and ks4 reuse (later iters)

        // Stage chunk c: 2048 float4, 16 per thread, coalesced gmem reads,
        // conflict-free swizzled smem writes.
#pragma unroll
        for (int i = 0; i < (KC * DK / 4) / 128; i++) {   // 16
            const int idx = tid + i * 128;
            const int kl  = idx >> 4;        // row within chunk
            const int d4  = idx & 15;        // float4 column
            ks4[kl][d4 ^ (kl & 7)] = ksrc[c * KC * (DK / 4) + idx];
        }
        __syncthreads();

        // Thread t computes scores for k = c*KC + t against all 6 q-rows.
        const int sw = tid & 7;
        float acc[QTA];
#pragma unroll
        for (int qq = 0; qq < QTA; qq++) acc[qq] = 0.0f;

#pragma unroll
        for (int i = 0; i < DK / 4; i++) {
            const float4 kv = ks4[tid][i ^ sw];     // conflict-free
#pragma unroll
            for (int qq = 0; qq < QTA; qq++) {
                const float4 a = qs4[qq][i];        // warp broadcast
                acc[qq] += a.x * kv.x + a.y * kv.y + a.z * kv.z + a.w * kv.w;
            }
        }
#pragma unroll
        for (int qq = 0; qq < QTA; qq++)
            scores[qq][c * KC + tid] = acc[qq] * INV_TEMP;
    }
    __syncthreads();

    // Softmax: 4 warps cover the 6 rows (warp w handles rows w, w+4).
    const int warp = tid >> 5;
    const int lane = tid & 31;
    for (int qq = warp; qq < QTA; qq += 4) {
        const float* row = scores[qq];

        float m = -CUDART_INF_F;
#pragma unroll
        for (int j = 0; j < LK / 32; j++) m = fmaxf(m, row[lane + j * 32]);
#pragma unroll
        for (int s = 16; s > 0; s >>= 1)
            m = fmaxf(m, __shfl_xor_sync(0xFFFFFFFFu, m, s));

        float e[LK / 32];
        float sum = 0.0f;
#pragma unroll
        for (int j = 0; j < LK / 32; j++) {
            e[j] = __expf(row[lane + j * 32] - m);
            sum += e[j];
        }
#pragma unroll
        for (int s = 16; s > 0; s >>= 1)
            sum += __shfl_xor_sync(0xFFFFFFFFu, sum, s);
        const float inv = 1.0f / sum;

        float* arow = attn + ((size_t)n * LQ + q0 + qq) * LK;
#pragma unroll
        for (int j = 0; j < LK / 32; j++)
            arow[lane + j * 32] = e[j] * inv;
    }
}

// ---------------------------------------------------------------------------
// Kernel B (UNCHANGED — measured 92.3-92.8us @ ~84% DRAM, 6.7 TB/s):
// out[n,q,d] = sum_k attn[n,q,k] * rel_pos_v[n,q,k,d]
// ---------------------------------------------------------------------------
__global__ __launch_bounds__(256, 8)
void out_kernel(const float* __restrict__ attn_ext_is_null_marker, // unused
                const float* __restrict__ rpv,
                float* __restrict__ out,
                const float* __restrict__ attn_ext)
{
    __shared__ float  sa[LK];       // attn row, 1.5 KB
    __shared__ float4 rbuf[256];    // reduction buffer, 4 KB

    const float* attn = attn_ext ? attn_ext : g_attn_scratch;

    const int nq  = blockIdx.x;            // n*LQ + q
    const int tid = threadIdx.x;

    {
        const float* arow = attn + (size_t)nq * LK;
        for (int j = tid; j < LK; j += 256) sa[j] = arow[j];
    }
    __syncthreads();

    const int d4 = tid & 15;   // float4 column (d = 4*d4 .. 4*d4+3)
    const int kk = tid >> 4;   // k-slice start (k = kk, kk+16, ...)

    const float4* base = reinterpret_cast<const float4*>(
        rpv + (size_t)nq * LK * DV);

    float4 acc = make_float4(0.f, 0.f, 0.f, 0.f);
#pragma unroll
    for (int i = 0; i < LK / 16; i++) {          // 24 iterations
        const int kidx = kk + i * 16;
        const float  a = sa[kidx];
        const float4 v = base[kidx * (DV / 4) + d4];
        acc.x += a * v.x;
        acc.y += a * v.y;
        acc.z += a * v.z;
        acc.w += a * v.w;
    }

    rbuf[tid] = acc;
    __syncthreads();

#pragma unroll
    for (int s = 128; s >= 16; s >>= 1) {
        if (tid < s) {
            float4 a = rbuf[tid];
            float4 b = rbuf[tid + s];
            a.x += b.x; a.y += b.y; a.z += b.z; a.w += b.w;
            rbuf[tid] = a;
        }
        __syncthreads();
    }

    if (tid < DV) {
        out[(size_t)nq * DV + tid] = reinterpret_cast<const float*>(rbuf)[tid];
    }
}

// ---------------------------------------------------------------------------
// Launch. Inputs (metadata order) = q, k, v, rel_pos, rel_pos_v.
// v and rel_pos are unused by the reference — never touched.
// Output layout: [output (NB*LQ*DV) | attn (NB*LQ*LK)] when out_size covers
// both (this branch passed in R3/R4); otherwise attn -> scratch.
// ---------------------------------------------------------------------------
extern "C" void kernel_launch(void* const* d_in, const int* in_sizes, int n_in,
                              void* d_out, int out_size)
{
    const float* q   = (const float*)d_in[0];
    const float* k   = (const float*)d_in[1];
    const float* rpv = (const float*)d_in[4];
    float* out = (float*)d_out;

    const long long out_elems  = (long long)NB * LQ * DV;   // 393216
    const long long attn_elems = (long long)NB * LQ * LK;   // 2359296

    float* attn_ext = nullptr;  // null -> kernels fall back to g_attn_scratch
    if ((long long)out_size >= out_elems + attn_elems) {
        attn_ext = out + out_elems;
    }

    dim3 gridA(LQ / QTA, NB);
    attn_kernel<<<gridA, 128>>>(q, k, attn_ext);

    out_kernel<<<NB * LQ, 256>>>(nullptr, rpv, out, attn_ext);
}

// round 7
// speedup vs baseline: 1.8501x; 1.0058x over previous
#include <cuda_runtime.h>
#include <math_constants.h>

// Problem constants (NB, LQ, LK, DK, DV = 16, 384, 384, 64, 64)
#define NB 16
#define LQ 384
#define LK 384
#define DK 64
#define DV 64
#define QTA 8            // q-rows per attn block (384/8=48 -> 768 blocks)
#define INV_TEMP 0.125f  // 1 / TEMPERATURE, TEMPERATURE = 8.0

// Scratch for attn probabilities in case the harness output only holds `output`.
__device__ float g_attn_scratch[NB * LQ * LK];

// Dynamic smem layout (floats):
//   qs4    : QTA*16 float4        =  512 floats (2 KB)
//   ks4    : LK*16 float4         = 6144 float4 (96 KB), XOR-swizzled cols
//   scores : QTA*LK floats        = 3072 floats (12 KB)
#define SMEM_Q4_OFF  0
#define SMEM_K4_OFF  (QTA * 16)                 // in float4 units
#define SMEM_SC_OFF  ((QTA * 16 + LK * 16) * 4) // in float units
#define ATTN_SMEM_BYTES ((QTA * 16 + LK * 16) * 16 + QTA * LK * 4)  // 112640

// ---------------------------------------------------------------------------
// Kernel A: attn[n,q,k] = softmax_k( (q[n,q,:] . k[n,k,:]) / 8 )
// grid = (48, 16) = 768 blocks, 128 threads, occ 2 (110 KB smem).
// R5 was LDS-bound (0.29 LDS.128 per FFMA, ~18us of LDS-unit time). Fix:
// register-tile 3 k-rows x 8 q-rows per thread -> 11 LDS.128 per 96 FFMA.
// Full K[n] (96 KB) staged once per block, coalesced, XOR swizzle d4^(k&7)
// so both staging stores and per-row reads are bank-conflict-free.
// ---------------------------------------------------------------------------
__global__ __launch_bounds__(128, 2)
void attn_kernel(const float* __restrict__ q,
                 const float* __restrict__ k,
                 float* __restrict__ attn_ext)
{
    extern __shared__ float4 smem4[];
    float4* qs4    = smem4 + SMEM_Q4_OFF;                    // [QTA][16]
    float4* ks4    = smem4 + SMEM_K4_OFF;                    // [LK][16] swizzled
    float*  scores = reinterpret_cast<float*>(smem4) + SMEM_SC_OFF; // [QTA][LK]

    float* attn = attn_ext ? attn_ext : g_attn_scratch;

    const int n   = blockIdx.y;
    const int q0  = blockIdx.x * QTA;
    const int tid = threadIdx.x;             // 0..127

    // Stage the 8 q-rows (128 float4, one per thread, coalesced).
    {
        const float4* qsrc = reinterpret_cast<const float4*>(
            q + ((size_t)n * LQ + q0) * DK);
        qs4[tid] = qsrc[tid];
    }

    // Stage all of K[n]: 6144 float4, 48 per thread, coalesced gmem reads,
    // swizzled conflict-free smem writes.
    {
        const float4* ksrc = reinterpret_cast<const float4*>(
            k + (size_t)n * LK * DK);
#pragma unroll
        for (int i = 0; i < (LK * DK / 4) / 128; i++) {   // 48
            const int idx = tid + i * 128;
            const int kl  = idx >> 4;        // k-row 0..383
            const int d4  = idx & 15;        // float4 column
            ks4[kl * 16 + (d4 ^ (kl & 7))] = ksrc[idx];
        }
    }
    __syncthreads();

    // Thread t computes scores for k-rows t, t+128, t+256 vs all 8 q-rows.
    {
        const int sw = tid & 7;              // (tid+128j)&7 == tid&7
        float acc[3][QTA];
#pragma unroll
        for (int j = 0; j < 3; j++)
#pragma unroll
            for (int qq = 0; qq < QTA; qq++) acc[j][qq] = 0.0f;

#pragma unroll
        for (int i = 0; i < DK / 4; i++) {
            float4 kv[3];
#pragma unroll
            for (int j = 0; j < 3; j++)
                kv[j] = ks4[(tid + j * 128) * 16 + (i ^ sw)];   // conflict-free
#pragma unroll
            for (int qq = 0; qq < QTA; qq++) {
                const float4 a = qs4[qq * 16 + i];              // warp broadcast
#pragma unroll
                for (int j = 0; j < 3; j++) {
                    acc[j][qq] += a.x * kv[j].x + a.y * kv[j].y
                                + a.z * kv[j].z + a.w * kv[j].w;
                }
            }
        }
#pragma unroll
        for (int j = 0; j < 3; j++)
#pragma unroll
            for (int qq = 0; qq < QTA; qq++)
                scores[qq * LK + (tid + j * 128)] = acc[j][qq] * INV_TEMP;
    }
    __syncthreads();

    // Softmax: 4 warps, warp w handles rows w and w+4.
    const int warp = tid >> 5;
    const int lane = tid & 31;
#pragma unroll
    for (int qq = warp; qq < QTA; qq += 4) {
        const float* row = scores + qq * LK;

        float m = -CUDART_INF_F;
#pragma unroll
        for (int j = 0; j < LK / 32; j++) m = fmaxf(m, row[lane + j * 32]);
#pragma unroll
        for (int s = 16; s > 0; s >>= 1)
            m = fmaxf(m, __shfl_xor_sync(0xFFFFFFFFu, m, s));

        float e[LK / 32];
        float sum = 0.0f;
#pragma unroll
        for (int j = 0; j < LK / 32; j++) {
            e[j] = __expf(row[lane + j * 32] - m);
            sum += e[j];
        }
#pragma unroll
        for (int s = 16; s > 0; s >>= 1)
            sum += __shfl_xor_sync(0xFFFFFFFFu, sum, s);
        const float inv = 1.0f / sum;

        float* arow = attn + ((size_t)n * LQ + q0 + qq) * LK;
#pragma unroll
        for (int j = 0; j < LK / 32; j++)
            arow[lane + j * 32] = e[j] * inv;
    }
}

// ---------------------------------------------------------------------------
// Kernel B (UNCHANGED — measured 91.7-92.8us @ ~85% DRAM, 6.7 TB/s):
// out[n,q,d] = sum_k attn[n,q,k] * rel_pos_v[n,q,k,d]
// ---------------------------------------------------------------------------
__global__ __launch_bounds__(256, 8)
void out_kernel(const float* __restrict__ attn_ext_is_null_marker, // unused
                const float* __restrict__ rpv,
                float* __restrict__ out,
                const float* __restrict__ attn_ext)
{
    __shared__ float  sa[LK];       // attn row, 1.5 KB
    __shared__ float4 rbuf[256];    // reduction buffer, 4 KB

    const float* attn = attn_ext ? attn_ext : g_attn_scratch;

    const int nq  = blockIdx.x;            // n*LQ + q
    const int tid = threadIdx.x;

    {
        const float* arow = attn + (size_t)nq * LK;
        for (int j = tid; j < LK; j += 256) sa[j] = arow[j];
    }
    __syncthreads();

    const int d4 = tid & 15;   // float4 column (d = 4*d4 .. 4*d4+3)
    const int kk = tid >> 4;   // k-slice start (k = kk, kk+16, ...)

    const float4* base = reinterpret_cast<const float4*>(
        rpv + (size_t)nq * LK * DV);

    float4 acc = make_float4(0.f, 0.f, 0.f, 0.f);
#pragma unroll
    for (int i = 0; i < LK / 16; i++) {          // 24 iterations
        const int kidx = kk + i * 16;
        const float  a = sa[kidx];
        const float4 v = base[kidx * (DV / 4) + d4];
        acc.x += a * v.x;
        acc.y += a * v.y;
        acc.z += a * v.z;
        acc.w += a * v.w;
    }

    rbuf[tid] = acc;
    __syncthreads();

#pragma unroll
    for (int s = 128; s >= 16; s >>= 1) {
        if (tid < s) {
            float4 a = rbuf[tid];
            float4 b = rbuf[tid + s];
            a.x += b.x; a.y += b.y; a.z += b.z; a.w += b.w;
            rbuf[tid] = a;
        }
        __syncthreads();
    }

    if (tid < DV) {
        out[(size_t)nq * DV + tid] = reinterpret_cast<const float*>(rbuf)[tid];
    }
}

// ---------------------------------------------------------------------------
// Launch. Inputs (metadata order) = q, k, v, rel_pos, rel_pos_v.
// v and rel_pos are unused by the reference — never touched.
// Output layout: [output (NB*LQ*DV) | attn (NB*LQ*LK)] when out_size covers
// both (this branch passed R3-R5); otherwise attn -> scratch.
// ---------------------------------------------------------------------------
extern "C" void kernel_launch(void* const* d_in, const int* in_sizes, int n_in,
                              void* d_out, int out_size)
{
    const float* q   = (const float*)d_in[0];
    const float* k   = (const float*)d_in[1];
    const float* rpv = (const float*)d_in[4];
    float* out = (float*)d_out;

    const long long out_elems  = (long long)NB * LQ * DV;   // 393216
    const long long attn_elems = (long long)NB * LQ * LK;   // 2359296

    float* attn_ext = nullptr;  // null -> kernels fall back to g_attn_scratch
    if ((long long)out_size >= out_elems + attn_elems) {
        attn_ext = out + out_elems;
    }

    // >48KB dynamic smem needs the attribute bump (host-side, capture-safe).
    static int smem_attr_set = 0;
    if (!smem_attr_set) {
        cudaFuncSetAttribute(attn_kernel,
                             cudaFuncAttributeMaxDynamicSharedMemorySize,
                             ATTN_SMEM_BYTES);
        smem_attr_set = 1;
    }

    dim3 gridA(LQ / QTA, NB);
    attn_kernel<<<gridA, 128, ATTN_SMEM_BYTES>>>(q, k, attn_ext);

    out_kernel<<<NB * LQ, 256>>>(nullptr, rpv, out, attn_ext);
}